// round 14
// baseline (speedup 1.0000x reference)
#include <cuda_runtime.h>
#include <math.h>

#define NB 1024
#define NC 100000
#define THREADS 256

// scratch (zero-initialized at module load; last block resets for replay)
static __device__ unsigned long long g_acc;   // fixed-point sum of nll
static __device__ unsigned int g_done;

// 64 * log2(e)
#define K2 92.33248261625200f
#define LOG2E 1.4426950408889634f
#define FXSCALE 1099511627776.0f              // 2^40
#define FXINV   (1.0 / 1099511627776.0)

__device__ __forceinline__ float ex2_fast(float x) {
    float y;
    asm("ex2.approx.ftz.f32 %0, %1;" : "=f"(y) : "f"(x));
    return y;
}

__device__ __forceinline__ float term(float v) {
    float c = fminf(fmaxf(v, -1.0f), 1.0f);
    return ex2_fast(fmaf(c, K2, -K2));   // exp(64*c - 64)
}

__global__ void __launch_bounds__(THREADS)
fused_loss_kernel(const float* __restrict__ x,
                  const int* __restrict__ label,
                  const float* __restrict__ margin,
                  float* __restrict__ out) {
    const int row = blockIdx.x;
    const float4* __restrict__ p =
        reinterpret_cast<const float4*>(x + (size_t)row * NC);
    const int n4 = NC / 4;  // 25000

    // 4 independent accumulators: breaks the serial FADD chain
    float s0 = 0.0f, s1 = 0.0f, s2 = 0.0f, s3 = 0.0f;
    #pragma unroll 8
    for (int i = threadIdx.x; i < n4; i += THREADS) {
        float4 v = __ldcs(p + i);
        s0 += term(v.x);
        s1 += term(v.y);
        s2 += term(v.z);
        s3 += term(v.w);
    }
    float s = (s0 + s1) + (s2 + s3);

    // block reduction
    __shared__ float red[THREADS / 32];
    const int lane = threadIdx.x & 31;
    const int wid  = threadIdx.x >> 5;
    #pragma unroll
    for (int o = 16; o; o >>= 1) s += __shfl_xor_sync(0xFFFFFFFFu, s, o);
    if (lane == 0) red[wid] = s;
    __syncthreads();

    if (wid == 0) {
        float t = (lane < THREADS / 32) ? red[lane] : 0.0f;
        #pragma unroll
        for (int o = (THREADS / 64); o; o >>= 1)
            t += __shfl_xor_sync(0xFFFFFFFFu, t, o);

        if (lane == 0) {
            int lb = __ldg(label + row);
            const bool valid = (lb >= 0);
            int tgt = valid ? lb : 0;
            tgt = min(max(tgt, 0), NC - 1);   // never fabricate OOB address
            const float mg = valid ? __ldg(margin + row) : 0.0f;

            float xt = __ldg(x + (size_t)row * NC + tgt);
            float c  = fminf(fmaxf(xt, -1.0f), 1.0f);
            float l_mod = 64.0f * cosf(acosf(c) + mg);

            // replace target term: subtract original, add modified
            float stot = t - ex2_fast(fmaf(c, K2, -K2))
                           + ex2_fast((l_mod - 64.0f) * LOG2E);

            float nll = 64.0f + logf(stot) - l_mod;   // >= 0 always

            // deterministic fixed-point accumulation (integer add = associative)
            atomicAdd(&g_acc, (unsigned long long)((double)nll * (double)FXSCALE));
            __threadfence();
            unsigned int done = atomicAdd(&g_done, 1u);

            // last block to finish emits the mean and resets scratch
            if (done == (unsigned int)(NB - 1)) {
                unsigned long long a;
                asm volatile("ld.acquire.gpu.global.u64 %0, [%1];"
                             : "=l"(a) : "l"(&g_acc) : "memory");
                out[0] = (float)((double)a * FXINV * (1.0 / (double)NB));
                g_acc  = 0ull;
                g_done = 0u;
            }
        }
    }
}

extern "C" void kernel_launch(void* const* d_in, const int* in_sizes, int n_in,
                              void* d_out, int out_size) {
    const float* x      = (const float*)d_in[0];
    const int*   label  = (const int*)d_in[1];
    const float* margin = (const float*)d_in[2];
    float*       out    = (float*)d_out;

    fused_loss_kernel<<<NB, THREADS>>>(x, label, margin, out);
}